// round 13
// baseline (speedup 1.0000x reference)
#include <cuda_runtime.h>
#include <cuda_bf16.h>
#include <cstdint>

// Problem constants (fixed shapes from reference setup_inputs)
constexpr int B  = 8;
constexpr int L  = 4096;
constexpr int D  = 64;
constexpr int LQ = 2744;            // int((1.0-0.33)*4096)
constexpr int NDROP = L - LQ;       // 1352

constexpr int NQT    = 11;          // ceil(2744/256)
constexpr int ROWS   = NQT * 256;   // 2816 slab rows per (slice,b)
constexpr int NSLICE = 8;           // key slices of 512
constexpr int TASKS  = B * NQT * NSLICE;  // 704
constexpr int NBLK   = 148;         // persistent blocks (<= SM count)

// ---------------- scratch (device globals; no allocations allowed) -------------
__device__ float g_QT[B * D * L];   // [b][d][l] fp32 (for sqk)
__device__ float g_KT[B * D * L];   // [b][d][l] fp32 (for kreduce)
__device__ float g_Kred[B * D];
__device__ uint32_t g_skey[B * L];  // sortable-encoded sqk keys
__device__ int   g_sel[B * LQ];
__device__ int   g_rowslot[B * L];  // slab row for selected l, else -1
__device__ float g_mean[B * D];

__device__ __nv_bfloat16 g_Qh[B * L * D];
__device__ __nv_bfloat16 g_Ql[B * L * D];
__device__ __nv_bfloat16 g_Kh[B * L * D];
__device__ __nv_bfloat16 g_Kl[B * L * D];
__device__ __nv_bfloat16 g_VTh[B * D * L];   // [b][d][l]
__device__ __nv_bfloat16 g_VTl[B * D * L];

__device__ float g_Oacc[NSLICE * B * ROWS * 64];   // ~46MB partial O sums
__device__ float g_lacc[NSLICE * B * ROWS];

// ============================ helpers =========================================
__device__ __forceinline__ uint32_t smem_u32(const void* p) {
    uint32_t a;
    asm("{ .reg .u64 t; cvta.to.shared.u64 t, %1; cvt.u32.u64 %0, t; }"
        : "=r"(a) : "l"(p));
    return a;
}

// bf16 split-pack: (a,b) -> packed bf16x2 hi and lo residual (precompute path)
__device__ __forceinline__ void split2(float a, float b, uint32_t& hi, uint32_t& lo) {
    __nv_bfloat16 ah = __float2bfloat16(a), bh = __float2bfloat16(b);
    float ar = a - __bfloat162float(ah);
    float br = b - __bfloat162float(bh);
    __nv_bfloat16 al = __float2bfloat16(ar), bl = __float2bfloat16(br);
    uint16_t ahu = *(uint16_t*)&ah, bhu = *(uint16_t*)&bh;
    uint16_t alu = *(uint16_t*)&al, blu = *(uint16_t*)&bl;
    hi = ((uint32_t)bhu << 16) | ahu;
    lo = ((uint32_t)blu << 16) | alu;
}

// fast P split: packed cvt (lo_v -> low half, hi_v -> high half)
__device__ __forceinline__ void psplit(float lo_v, float hi_v,
                                       uint32_t& h, uint32_t& l) {
    asm("cvt.rn.bf16x2.f32 %0, %1, %2;" : "=r"(h) : "f"(hi_v), "f"(lo_v));
    float fl = __uint_as_float(h << 16);
    float fh = __uint_as_float(h & 0xFFFF0000u);
    asm("cvt.rn.bf16x2.f32 %0, %1, %2;" : "=r"(l) : "f"(hi_v - fh), "f"(lo_v - fl));
}

__device__ __forceinline__ float inv_sortable(uint32_t u) {
    return (u & 0x80000000u) ? __uint_as_float(u & 0x7FFFFFFFu) : __uint_as_float(~u);
}

// warp-aggregated histogram add: one same-address atomic per distinct bin/warp
__device__ __forceinline__ void hist_add(uint32_t* hist, bool act, uint32_t bin,
                                         int lane) {
    unsigned am = __ballot_sync(0xffffffffu, act);
    if (act) {
        unsigned mm = __match_any_sync(am, bin);
        int leader = __ffs(mm) - 1;
        if (lane == leader) atomicAdd(&hist[bin], (uint32_t)__popc(mm));
    }
}

#define LDSM_X4(r0, r1, r2, r3, addr) \
    asm volatile("ldmatrix.sync.aligned.m8n8.x4.shared.b16 {%0,%1,%2,%3}, [%4];" \
        : "=r"(r0), "=r"(r1), "=r"(r2), "=r"(r3) : "r"(addr))

#define MMA_BF16(c, a, b) \
    asm volatile("mma.sync.aligned.m16n8k16.row.col.f32.bf16.bf16.f32 " \
        "{%0,%1,%2,%3}, {%4,%5,%6,%7}, {%8,%9}, {%0,%1,%2,%3};" \
        : "+f"((c)[0]), "+f"((c)[1]), "+f"((c)[2]), "+f"((c)[3]) \
        : "r"((a)[0]), "r"((a)[1]), "r"((a)[2]), "r"((a)[3]), \
          "r"((b)[0]), "r"((b)[1]))

__device__ __forceinline__ void cp16(uint32_t dst, const void* src) {
    asm volatile("cp.async.cg.shared.global [%0], [%1], 16;"
                 :: "r"(dst), "l"(__cvta_generic_to_global(src)) : "memory");
}
#define CP_COMMIT() asm volatile("cp.async.commit_group;" ::: "memory")
#define CP_WAIT1()  asm volatile("cp.async.wait_group 1;" ::: "memory")
#define CP_WAIT0()  asm volatile("cp.async.wait_group 0;" ::: "memory")

// ---------------- 1) fused QKV projection + splits + transposes ---------------
constexpr int PREP_XS   = 64 * 129;               // floats
constexpr int PREP_SMEM = (PREP_XS + 3 * 4096) * 4;   // 82176 B

__global__ __launch_bounds__(512) void prep_kernel(const float* __restrict__ x,
                                                   const float* __restrict__ Wq,
                                                   const float* __restrict__ Wk,
                                                   const float* __restrict__ Wv) {
    extern __shared__ float smf[];
    float* xsT = smf;                 // [64][129]
    float* Ws  = smf + PREP_XS;       // [3][64][64]

    const int tid  = threadIdx.x;
    const int row0 = blockIdx.x * 128;
    const int b    = row0 >> 12;
    const int l0   = row0 & (L - 1);

    for (int i = tid; i < 4096; i += 512) {
        Ws[i]        = Wq[i];
        Ws[4096 + i] = Wk[i];
        Ws[8192 + i] = Wv[i];
    }
    const int c = tid & 63, rg = tid >> 6;     // rg 0..7
    {
#pragma unroll
        for (int rr = 0; rr < 16; rr++) {
            int r = rg * 16 + rr;
            xsT[c * 129 + r] = x[(size_t)(row0 + r) * 64 + c];
        }
    }
    __syncthreads();

    const float* xrow = xsT + rg * 16;
    const size_t ot = ((size_t)b * 64 + c) * (size_t)L + l0 + rg * 16;

#pragma unroll
    for (int m = 0; m < 3; m++) {
        float acc[16];
#pragma unroll
        for (int i = 0; i < 16; i++) acc[i] = 0.f;
        const float* Wm = Ws + m * 4096 + c;
#pragma unroll 4
        for (int d = 0; d < 64; d++) {
            float w = Wm[d * 64];
#pragma unroll
            for (int rr = 0; rr < 16; rr++)
                acc[rr] += xrow[d * 129 + rr] * w;
        }

        if (m == 0) {            // Q: transposed fp32 + scaled hi/lo split
            float4* dq = (float4*)(g_QT + ot);
#pragma unroll
            for (int q = 0; q < 4; q++)
                dq[q] = make_float4(acc[4 * q], acc[4 * q + 1],
                                    acc[4 * q + 2], acc[4 * q + 3]);
#pragma unroll
            for (int rr = 0; rr < 16; rr++) {
                size_t idx = (size_t)(row0 + rg * 16 + rr) * 64 + c;
                float v = acc[rr] * 0.125f;
                __nv_bfloat16 h = __float2bfloat16(v);
                g_Qh[idx] = h;
                g_Ql[idx] = __float2bfloat16(v - __bfloat162float(h));
            }
        } else if (m == 1) {     // K: transposed fp32 + hi/lo split
            float4* dk = (float4*)(g_KT + ot);
#pragma unroll
            for (int q = 0; q < 4; q++)
                dk[q] = make_float4(acc[4 * q], acc[4 * q + 1],
                                    acc[4 * q + 2], acc[4 * q + 3]);
#pragma unroll
            for (int rr = 0; rr < 16; rr++) {
                size_t idx = (size_t)(row0 + rg * 16 + rr) * 64 + c;
                __nv_bfloat16 h = __float2bfloat16(acc[rr]);
                g_Kh[idx] = h;
                g_Kl[idx] = __float2bfloat16(acc[rr] - __bfloat162float(h));
            }
        } else {                 // V: transposed hi/lo split only
            uint32_t hw[8], lw[8];
#pragma unroll
            for (int j = 0; j < 8; j++)
                split2(acc[2 * j], acc[2 * j + 1], hw[j], lw[j]);
            uint4* dh = (uint4*)((char*)g_VTh + ot * 2);
            uint4* dl = (uint4*)((char*)g_VTl + ot * 2);
#pragma unroll
            for (int q = 0; q < 2; q++) {
                dh[q] = make_uint4(hw[4 * q], hw[4 * q + 1], hw[4 * q + 2], hw[4 * q + 3]);
                dl[q] = make_uint4(lw[4 * q], lw[4 * q + 1], lw[4 * q + 2], lw[4 * q + 3]);
            }
        }
    }
}

// ---------------- 2) K_reduce (radix select) + meanv folded in ----------------
// grid = B*D + B*8: first 512 blocks do kreduce, last 64 do meanv.
__global__ __launch_bounds__(256) void kreduce_kernel() {
    if (blockIdx.x >= B * D) {
        // ---- meanv: mean of V from transposed bf16 splits ----
        const int bid = blockIdx.x - B * D;
        const int b = bid >> 3, dg = bid & 7;
        const int tid = threadIdx.x;
        const int d = dg * 8 + (tid >> 5), lane = tid & 31;

        const size_t rowb = ((size_t)b * 64 + d) * (size_t)L;   // bf16 elems
        const uint4* rh = (const uint4*)((const char*)g_VTh + rowb * 2);
        const uint4* rl = (const uint4*)((const char*)g_VTl + rowb * 2);

        float s = 0.f;
#pragma unroll
        for (int it = 0; it < 16; it++) {
            uint4 h = rh[lane + 32 * it];
            uint4 lo = rl[lane + 32 * it];
            const uint32_t hw[4] = {h.x, h.y, h.z, h.w};
            const uint32_t lw[4] = {lo.x, lo.y, lo.z, lo.w};
#pragma unroll
            for (int q = 0; q < 4; q++) {
                s += __uint_as_float(hw[q] << 16) + __uint_as_float(hw[q] & 0xFFFF0000u);
                s += __uint_as_float(lw[q] << 16) + __uint_as_float(lw[q] & 0xFFFF0000u);
            }
        }
#pragma unroll
        for (int o = 16; o > 0; o >>= 1)
            s += __shfl_xor_sync(0xffffffffu, s, o);
        if (lane == 0) g_mean[b * 64 + d] = s * (1.0f / (float)L);
        return;
    }

    __shared__ uint32_t key[4096];
    __shared__ uint32_t hist[256];
    __shared__ uint32_t wsum[8];
    __shared__ float    fsum[8];
    __shared__ int      csum[8];
    __shared__ uint32_t sh_prefix;
    __shared__ int      sh_r;

    const int tid = threadIdx.x, lane = tid & 31;
    const int b = blockIdx.x >> 6, d = blockIdx.x & 63;
    const float* Kr = g_KT + ((size_t)b * 64 + d) * (size_t)L;   // contiguous row

    for (int i = tid; i < 4096; i += 256) {
        uint32_t u = __float_as_uint(Kr[i]);
        key[i] = (u & 0x80000000u) ? ~u : (u | 0x80000000u);
    }
    if (tid == 0) { sh_r = NDROP; sh_prefix = 0; }
    __syncthreads();

    for (int shift = 24; shift >= 0; shift -= 8) {
        int r = sh_r;
        uint32_t pfx = sh_prefix;
        hist[tid] = 0;
        __syncthreads();
        for (int i = tid; i < 4096; i += 256) {
            uint32_t u = key[i];
            bool act = (shift == 24) || ((u >> (shift + 8)) == pfx);
            hist_add(hist, act, (u >> shift) & 255u, lane);
        }
        __syncthreads();
        uint32_t h = hist[tid], v = h;
#pragma unroll
        for (int o = 1; o < 32; o <<= 1) {
            uint32_t n = __shfl_up_sync(0xffffffffu, v, o);
            if (lane >= o) v += n;
        }
        if (lane == 31) wsum[tid >> 5] = v;
        __syncthreads();
        uint32_t woff = 0;
        for (int w = 0; w < (tid >> 5); w++) woff += wsum[w];
        uint32_t incl = v + woff, excl = incl - h;
        if ((uint32_t)r >= excl && (uint32_t)r < incl) {
            sh_prefix = (pfx << 8) | (uint32_t)tid;
            sh_r = r - (int)excl;
        }
        __syncthreads();
    }

    uint32_t vb = sh_prefix;
    float s = 0.f; int c = 0;
    for (int i = tid; i < 4096; i += 256) {
        uint32_t u = key[i];
        if (u > vb) { s += inv_sortable(u); c++; }
    }
#pragma unroll
    for (int o = 16; o > 0; o >>= 1) {
        s += __shfl_xor_sync(0xffffffffu, s, o);
        c += __shfl_xor_sync(0xffffffffu, c, o);
    }
    if (lane == 0) { fsum[tid >> 5] = s; csum[tid >> 5] = c; }
    __syncthreads();
    if (tid == 0) {
        float st = 0.f; int ct = 0;
        for (int w = 0; w < 8; w++) { st += fsum[w]; ct += csum[w]; }
        g_Kred[b * 64 + d] =
            (st + (float)(LQ - ct) * inv_sortable(vb)) * (1.0f / (float)LQ);
    }
}

// ---------------- 3) wide sqk: keys for all (b,l), 32 blocks ------------------
__global__ __launch_bounds__(256) void sqk_kernel() {
    __shared__ float krs[64];
    const int tid = threadIdx.x;
    const int b = blockIdx.x >> 2, seg = blockIdx.x & 3;
    if (tid < 64) krs[tid] = g_Kred[b * 64 + tid];
    __syncthreads();

    const int l0 = seg * 1024 + tid * 4;
    const float* QT = g_QT + (size_t)b * 64 * (size_t)L + l0;
    float a0 = 0.f, a1 = 0.f, a2 = 0.f, a3 = 0.f;
#pragma unroll 4
    for (int d = 0; d < 64; d++) {
        float w = krs[d];
        float4 q = *(const float4*)(QT + (size_t)d * L);
        a0 += q.x * w; a1 += q.y * w; a2 += q.z * w; a3 += q.w * w;
    }
    float acc[4] = {a0, a1, a2, a3};
    uint32_t k[4];
#pragma unroll
    for (int j = 0; j < 4; j++) {
        uint32_t u = __float_as_uint(acc[j]);
        k[j] = (u & 0x80000000u) ? ~u : (u | 0x80000000u);
    }
    *(uint4*)(g_skey + b * L + l0) = make_uint4(k[0], k[1], k[2], k[3]);
}

// ---------------- 4) top-LQ selection: radix + aggregated scatter + tie scan --
__global__ __launch_bounds__(256) void select_kernel() {
    __shared__ uint32_t key[4096];
    __shared__ uint32_t hist[256];
    __shared__ uint32_t wsum[8];
    __shared__ uint32_t sh_prefix;
    __shared__ int      sh_r, nsel;

    const int tid = threadIdx.x, lane = tid & 31, warp = tid >> 5;
    const int b = blockIdx.x;
    const unsigned FULL = 0xffffffffu;

    for (int i = tid; i < 4096; i += 256)
        key[i] = g_skey[b * L + i];
    if (tid == 0) { sh_r = NDROP; sh_prefix = 0; nsel = 0; }
    __syncthreads();

    for (int shift = 24; shift >= 0; shift -= 8) {
        int r = sh_r;
        uint32_t pfx = sh_prefix;
        hist[tid] = 0;
        __syncthreads();
        for (int i = tid; i < 4096; i += 256) {
            uint32_t u = key[i];
            bool act = (shift == 24) || ((u >> (shift + 8)) == pfx);
            hist_add(hist, act, (u >> shift) & 255u, lane);
        }
        __syncthreads();
        uint32_t h = hist[tid], v = h;
#pragma unroll
        for (int o = 1; o < 32; o <<= 1) {
            uint32_t n = __shfl_up_sync(FULL, v, o);
            if (lane >= o) v += n;
        }
        if (lane == 31) wsum[warp] = v;
        __syncthreads();
        uint32_t woff = 0;
        for (int w = 0; w < warp; w++) woff += wsum[w];
        uint32_t incl = v + woff, excl = incl - h;
        if ((uint32_t)r >= excl && (uint32_t)r < incl) {
            sh_prefix = (pfx << 8) | (uint32_t)tid;
            sh_r = r - (int)excl;
        }
        __syncthreads();
    }

    const uint32_t vb = sh_prefix;

    // strict-above scatter: warp-aggregated atomic (set identical; order
    // irrelevant because rowslot keeps the sel<->slot mapping consistent)
#pragma unroll
    for (int it = 0; it < 16; it++) {
        int i = it * 256 + tid;
        bool f = (key[i] > vb);
        unsigned m = __ballot_sync(FULL, f);
        int rs = -1;
        if (m) {
            int leader = __ffs(m) - 1;
            int base = 0;
            if (lane == leader) base = atomicAdd(&nsel, __popc(m));
            base = __shfl_sync(FULL, base, leader);
            if (f) {
                int p = base + __popc(m & ((1u << lane) - 1u));
                g_sel[b * LQ + p] = i;
                rs = p;
            }
        }
        g_rowslot[b * L + i] = rs;
    }
    __syncthreads();

    // ties: single block-scan in index order (smallest indices first)
    {
        const int i0 = tid * 16;
        int cnt = 0;
#pragma unroll
        for (int j = 0; j < 16; j++) cnt += (key[i0 + j] == vb);
        int v = cnt;
#pragma unroll
        for (int o = 1; o < 32; o <<= 1) {
            int n = __shfl_up_sync(FULL, v, o);
            if (lane >= o) v += n;
        }
        if (lane == 31) wsum[warp] = (uint32_t)v;
        __syncthreads();
        int woff = 0;
        for (int w = 0; w < warp; w++) woff += (int)wsum[w];
        int r = v + woff - cnt;                 // exclusive rank in index order
        const int base = nsel, need = LQ - nsel;
#pragma unroll
        for (int j = 0; j < 16; j++) {
            int i = i0 + j;
            if (key[i] == vb) {
                if (r < need) {
                    g_sel[b * LQ + base + r] = i;
                    g_rowslot[b * L + i] = base + r;
                }
                r++;
            }
        }
    }
}

// ---------------- 5) persistent HMMA flash attention (pipelined) ---------------
// Contiguous task ranges (tile-major): a block's tasks share q-tiles, so Q
// gather + Q-LDSM run once per tile instead of once per task. Per-task math
// and slab targets identical -> bitwise-identical output.
constexpr int S_QL   = 36864;
constexpr int S_K0   = 73728;
constexpr int SO_VH  = 36864;        // within stage
constexpr int STG    = 71680;        // 2*18432 + 2*17408
constexpr int SMEM_ATTN = S_K0 + 2 * STG;   // 217088

__device__ __forceinline__ void stage_load(uint32_t sbase, int b, int k0, int tid) {
#pragma unroll
    for (int c = 0; c < 4; c++) {
        int ch = tid + 256 * c;                 // 0..1023
        int row = ch >> 3, off = ch & 7;
        size_t gi = ((size_t)b * L + k0 + row) * 64 + off * 8;
        uint32_t dk = sbase + (uint32_t)(row * 144 + off * 16);
        cp16(dk,          g_Kh + gi);
        cp16(dk + 18432u, g_Kl + gi);
    }
#pragma unroll
    for (int c = 0; c < 4; c++) {
        int ch = tid + 256 * c;                 // 0..1023
        int dd = ch >> 4, off = ch & 15;
        size_t gi = ((size_t)b * 64 + dd) * (size_t)L + k0 + off * 8;
        uint32_t dv = sbase + (uint32_t)SO_VH + (uint32_t)(dd * 272 + off * 16);
        cp16(dv,          g_VTh + gi);
        cp16(dv + 17408u, g_VTl + gi);
    }
}

#define S_CHUNK(sarr, cc, kab) do { \
    uint32_t bh[4], bl[4]; \
    LDSM_X4(bh[0], bh[1], bh[2], bh[3], (kab) + (cc) * 32); \
    LDSM_X4(bl[0], bl[1], bl[2], bl[3], (kab) + (cc) * 32 + 18432u); \
    MMA_BF16((sarr)[0][0], qh[0][cc], bh); \
    MMA_BF16((sarr)[1][0], qh[1][cc], bh); \
    MMA_BF16((sarr)[0][1], qh[0][cc], bh + 2); \
    MMA_BF16((sarr)[1][1], qh[1][cc], bh + 2); \
    MMA_BF16((sarr)[0][0], qh[0][cc], bl); \
    MMA_BF16((sarr)[1][0], qh[1][cc], bl); \
    MMA_BF16((sarr)[0][1], qh[0][cc], bl + 2); \
    MMA_BF16((sarr)[1][1], qh[1][cc], bl + 2); \
    MMA_BF16((sarr)[0][0], ql[0][cc], bh); \
    MMA_BF16((sarr)[1][0], ql[1][cc], bh); \
    MMA_BF16((sarr)[0][1], ql[0][cc], bh + 2); \
    MMA_BF16((sarr)[1][1], ql[1][cc], bh + 2); \
} while (0)

#define PV_CHUNK(jp, vab) do { \
    uint32_t bvh[4], bvl[4]; \
    uint32_t a_ = (vab) + (uint32_t)((jp) * 16) * 272; \
    LDSM_X4(bvh[0], bvh[1], bvh[2], bvh[3], a_); \
    LDSM_X4(bvl[0], bvl[1], bvl[2], bvl[3], a_ + 17408u); \
    MMA_BF16(oacc[0][2 * (jp)],     pah[0], bvh); \
    MMA_BF16(oacc[1][2 * (jp)],     pah[1], bvh); \
    MMA_BF16(oacc[0][2 * (jp) + 1], pah[0], bvh + 2); \
    MMA_BF16(oacc[1][2 * (jp) + 1], pah[1], bvh + 2); \
    MMA_BF16(oacc[0][2 * (jp)],     pah[0], bvl); \
    MMA_BF16(oacc[1][2 * (jp)],     pah[1], bvl); \
    MMA_BF16(oacc[0][2 * (jp) + 1], pah[0], bvl + 2); \
    MMA_BF16(oacc[1][2 * (jp) + 1], pah[1], bvl + 2); \
    MMA_BF16(oacc[0][2 * (jp)],     pal[0], bvh); \
    MMA_BF16(oacc[1][2 * (jp)],     pal[1], bvh); \
    MMA_BF16(oacc[0][2 * (jp) + 1], pal[0], bvh + 2); \
    MMA_BF16(oacc[1][2 * (jp) + 1], pal[1], bvh + 2); \
} while (0)

__global__ __launch_bounds__(256, 1) void attn_kernel() {
    extern __shared__ __align__(16) char sm[];

    const int tid = threadIdx.x, wid = tid >> 5, lane = tid & 31;
    const uint32_t smb = smem_u32(sm);

    const int start = (blockIdx.x * TASKS) / NBLK;
    const int stop  = ((blockIdx.x + 1) * TASKS) / NBLK;

    const uint32_t koff = (uint32_t)((lane & 7) + ((lane >> 4) & 1) * 8) * 144 +
                          ((lane >> 3) & 1) * 16;
    const uint32_t voff = (uint32_t)((lane & 7) + ((lane >> 4) & 1) * 8) * 272 +
                          ((lane >> 3) & 1) * 16;

    uint32_t qh[2][4][4], ql[2][4][4];   // persist across same-tile tasks
    int prev_tile = -1;

    for (int tsk = start; tsk < stop; tsk++) {
        const int tile = tsk >> 3, slice = tsk & 7;
        const int b = tile / NQT, qt = tile - b * NQT;
        const int k0b = slice * 512;
        const bool newQ = (tile != prev_tile);
        prev_tile = tile;

        if (newQ) {
            // Q gather (hi/lo) via cp.async; g_sel read inline (no smem qidx)
#pragma unroll
            for (int c = 0; c < 8; c++) {
                int ch = tid + 256 * c;          // 0..2047
                int row = ch >> 3, off = ch & 7;
                int g = qt * 256 + row;
                int sel = g_sel[b * LQ + (g < LQ ? g : LQ - 1)];
                size_t gi = ((size_t)b * L + sel) * 64 + off * 8;
                uint32_t dq = smb + (uint32_t)(row * 144 + off * 16);
                cp16(dq,                  g_Qh + gi);
                cp16(dq + (uint32_t)S_QL, g_Ql + gi);
            }
            CP_COMMIT();
        }
        stage_load(smb + S_K0, b, k0b, tid);     // stage 0
        CP_COMMIT();

        if (newQ) {
            CP_WAIT1();                           // Q complete (s0 may pend)
            __syncthreads();
#pragma unroll
            for (int mt = 0; mt < 2; mt++) {
                uint32_t rsel = (uint32_t)(wid * 32 + mt * 16 + (lane & 7) +
                                           ((lane >> 3) & 1) * 8);
                uint32_t csel = ((lane >> 4) & 1) * 16;
#pragma unroll
                for (int c = 0; c < 4; c++) {
                    uint32_t a = smb + rsel * 144 + c * 32 + csel;
                    LDSM_X4(qh[mt][c][0], qh[mt][c][1], qh[mt][c][2], qh[mt][c][3], a);
                    LDSM_X4(ql[mt][c][0], ql[mt][c][1], ql[mt][c][2], ql[mt][c][3],
                            a + (uint32_t)S_QL);
                }
            }
        }

        float oacc[2][8][4];
#pragma unroll
        for (int mt = 0; mt < 2; mt++)
#pragma unroll
            for (int j = 0; j < 8; j++)
#pragma unroll
                for (int i = 0; i < 4; i++) oacc[mt][j][i] = 0.f;
        float ls[2][2] = {{0.f, 0.f}, {0.f, 0.f}};

        for (int t = 0; t < 4; t++) {
            if (t < 3) {
                stage_load(smb + S_K0 + (uint32_t)(((t + 1) & 1) * STG),
                           b, k0b + (t + 1) * 128, tid);
                CP_COMMIT();
                CP_WAIT1();                       // stage t complete
            } else {
                CP_WAIT0();
            }
            __syncthreads();

            const uint32_t sb = smb + S_K0 + (uint32_t)((t & 1) * STG);
            const uint32_t kabase = sb + koff;
            const uint32_t vabase = sb + (uint32_t)SO_VH + voff;

            // ---- prolog: S(kc=0) into s[0] ----
            float s[2][2][2][4];
#pragma unroll
            for (int mt = 0; mt < 2; mt++)
#pragma unroll
                for (int j = 0; j < 2; j++)
#pragma unroll
                    for (int i = 0; i < 4; i++) s[0][mt][j][i] = 0.f;
#pragma unroll
            for (int c = 0; c < 4; c++) S_CHUNK(s[0], c, kabase);

#pragma unroll
            for (int kc = 0; kc < 8; kc++) {
                const int cur = kc & 1, nxt = cur ^ 1;

                // ---- softmax of kc (data ready since mid iter kc-1) ----
                uint32_t pah[2][4], pal[2][4];
#pragma unroll
                for (int mt = 0; mt < 2; mt++) {
                    float e00 = __expf(s[cur][mt][0][0]), e01 = __expf(s[cur][mt][0][1]);
                    float e02 = __expf(s[cur][mt][0][2]), e03 = __expf(s[cur][mt][0][3]);
                    float e10 = __expf(s[cur][mt][1][0]), e11 = __expf(s[cur][mt][1][1]);
                    float e12 = __expf(s[cur][mt][1][2]), e13 = __expf(s[cur][mt][1][3]);
                    ls[mt][0] += e00 + e01 + e10 + e11;
                    ls[mt][1] += e02 + e03 + e12 + e13;
                    psplit(e00, e01, pah[mt][0], pal[mt][0]);
                    psplit(e02, e03, pah[mt][1], pal[mt][1]);
                    psplit(e10, e11, pah[mt][2], pal[mt][2]);
                    psplit(e12, e13, pah[mt][3], pal[mt][3]);
                }

                const uint32_t vac = vabase + (uint32_t)(kc * 32);
                if (kc < 7) {
#pragma unroll
                    for (int mt = 0; mt < 2; mt++)
#pragma unroll
                        for (int j = 0; j < 2; j++)
#pragma unroll
                            for (int i = 0; i < 4; i++) s[nxt][mt][j][i] = 0.f;
                    const uint32_t kan = kabase + (uint32_t)(16 * (kc + 1)) * 144;
#pragma unroll
                    for (int i = 0; i < 4; i++) {
                        S_CHUNK(s[nxt], i, kan);   // next-kc S, fills tensor pipe
                        PV_CHUNK(i, vac);          // current-kc PV
                    }
                } else {
#pragma unroll
                    for (int i = 0; i < 4; i++) PV_CHUNK(i, vac);
                }
            }
            __syncthreads();
        }

        // epilogue: partial (O, l) to this slice's slab (no atomics)
#pragma unroll
        for (int mt = 0; mt < 2; mt++) {
            float l0 = ls[mt][0], l1 = ls[mt][1];
            l0 += __shfl_xor_sync(0xffffffffu, l0, 1);
            l0 += __shfl_xor_sync(0xffffffffu, l0, 2);
            l1 += __shfl_xor_sync(0xffffffffu, l1, 1);
            l1 += __shfl_xor_sync(0xffffffffu, l1, 2);

            const int r0 = wid * 32 + mt * 16 + (lane >> 2), r1 = r0 + 8;
            const size_t slab = (size_t)(slice * B + b) * ROWS;
            const int gq0 = qt * 256 + r0, gq1 = qt * 256 + r1;
            float* O0 = g_Oacc + (slab + gq0) * 64 + (lane & 3) * 2;
            float* O1 = g_Oacc + (slab + gq1) * 64 + (lane & 3) * 2;
#pragma unroll
            for (int jd = 0; jd < 8; jd++) {
                *(float2*)(O0 + jd * 8) = make_float2(oacc[mt][jd][0], oacc[mt][jd][1]);
                *(float2*)(O1 + jd * 8) = make_float2(oacc[mt][jd][2], oacc[mt][jd][3]);
            }
            if ((lane & 3) == 0) {
                g_lacc[slab + gq0] = l0;
                g_lacc[slab + gq1] = l1;
            }
        }
    }
}

// ---------------- 6) output: mean or normalized attention per row -------------
__global__ __launch_bounds__(256) void output_kernel(float* __restrict__ out) {
    int u = blockIdx.x * 256 + threadIdx.x;       // float4 units, B*L*16 total
    int d4 = u & 15;
    int row = u >> 4;                              // b*L + l
    int b = row >> 12;
    int slot = g_rowslot[row];

    float4 w;
    if (slot < 0) {
        w = ((const float4*)(g_mean + b * 64))[d4];
    } else {
        float4 o = make_float4(0.f, 0.f, 0.f, 0.f);
        float l = 0.f;
#pragma unroll
        for (int s = 0; s < NSLICE; s++) {
            size_t base = (size_t)(s * B + b) * ROWS + slot;
            float4 p = ((const float4*)(g_Oacc + base * 64))[d4];
            o.x += p.x; o.y += p.y; o.z += p.z; o.w += p.w;
            l += g_lacc[base];
        }
        float inv = 1.0f / l;
        w = make_float4(o.x * inv, o.y * inv, o.z * inv, o.w * inv);
    }
    ((float4*)out)[u] = w;
}

// ---------------- launcher ----------------------------------------------------
extern "C" void kernel_launch(void* const* d_in, const int* in_sizes, int n_in,
                              void* d_out, int out_size) {
    const float* x  = (const float*)d_in[0];
    const float* Wq = (const float*)d_in[1];
    const float* Wk = (const float*)d_in[2];
    const float* Wv = (const float*)d_in[3];
    float* out = (float*)d_out;

    cudaFuncSetAttribute(prep_kernel,
                         cudaFuncAttributeMaxDynamicSharedMemorySize, PREP_SMEM);
    cudaFuncSetAttribute(attn_kernel,
                         cudaFuncAttributeMaxDynamicSharedMemorySize, SMEM_ATTN);

    prep_kernel<<<(B * L) / 128, 512, PREP_SMEM>>>(x, Wq, Wk, Wv);   // 1
    kreduce_kernel<<<B * D + B * 8, 256>>>();                        // 2 (+meanv)
    sqk_kernel<<<B * 4, 256>>>();                                    // 3
    select_kernel<<<B, 256>>>();                                     // 4 <- profiled
    attn_kernel<<<NBLK, 256, SMEM_ATTN>>>();                         // 5
    output_kernel<<<(B * L * 16) / 256, 256>>>(out);                 // 6
}

// round 14
// speedup vs baseline: 1.0551x; 1.0551x over previous
#include <cuda_runtime.h>
#include <cuda_bf16.h>
#include <cstdint>

// Problem constants (fixed shapes from reference setup_inputs)
constexpr int B  = 8;
constexpr int L  = 4096;
constexpr int D  = 64;
constexpr int LQ = 2744;            // int((1.0-0.33)*4096)
constexpr int NDROP = L - LQ;       // 1352

constexpr int NQT    = 11;          // ceil(2744/256)
constexpr int ROWS   = NQT * 256;   // 2816 slab rows per (slice,b)
constexpr int NSLICE = 8;           // key slices of 512
constexpr int TASKS  = B * NQT * NSLICE;  // 704
constexpr int NBLK   = 148;         // persistent blocks (<= SM count)

// ---------------- scratch (device globals; no allocations allowed) -------------
__device__ float g_QT[B * D * L];   // [b][d][l] fp32 (for sqk)
__device__ float g_KT[B * D * L];   // [b][d][l] fp32 (for kreduce)
__device__ float g_Kred[B * D];
__device__ uint32_t g_skey[B * L];  // sortable-encoded sqk keys
__device__ int   g_sel[B * LQ];
__device__ int   g_rowslot[B * L];  // slab row for selected l, else -1
__device__ float g_mean[B * D];

__device__ __nv_bfloat16 g_Qh[B * L * D];
__device__ __nv_bfloat16 g_Ql[B * L * D];
__device__ __nv_bfloat16 g_Kh[B * L * D];
__device__ __nv_bfloat16 g_Kl[B * L * D];
__device__ __nv_bfloat16 g_VTh[B * D * L];   // [b][d][l]
__device__ __nv_bfloat16 g_VTl[B * D * L];

__device__ float g_Oacc[NSLICE * B * ROWS * 64];   // ~46MB partial O sums
__device__ float g_lacc[NSLICE * B * ROWS];

// ============================ helpers =========================================
__device__ __forceinline__ uint32_t smem_u32(const void* p) {
    uint32_t a;
    asm("{ .reg .u64 t; cvta.to.shared.u64 t, %1; cvt.u32.u64 %0, t; }"
        : "=r"(a) : "l"(p));
    return a;
}

// bf16 split-pack: (a,b) -> packed bf16x2 hi and lo residual (precompute path)
__device__ __forceinline__ void split2(float a, float b, uint32_t& hi, uint32_t& lo) {
    __nv_bfloat16 ah = __float2bfloat16(a), bh = __float2bfloat16(b);
    float ar = a - __bfloat162float(ah);
    float br = b - __bfloat162float(bh);
    __nv_bfloat16 al = __float2bfloat16(ar), bl = __float2bfloat16(br);
    uint16_t ahu = *(uint16_t*)&ah, bhu = *(uint16_t*)&bh;
    uint16_t alu = *(uint16_t*)&al, blu = *(uint16_t*)&bl;
    hi = ((uint32_t)bhu << 16) | ahu;
    lo = ((uint32_t)blu << 16) | alu;
}

// fast P split: packed cvt (lo_v -> low half, hi_v -> high half)
__device__ __forceinline__ void psplit(float lo_v, float hi_v,
                                       uint32_t& h, uint32_t& l) {
    asm("cvt.rn.bf16x2.f32 %0, %1, %2;" : "=r"(h) : "f"(hi_v), "f"(lo_v));
    float fl = __uint_as_float(h << 16);
    float fh = __uint_as_float(h & 0xFFFF0000u);
    asm("cvt.rn.bf16x2.f32 %0, %1, %2;" : "=r"(l) : "f"(hi_v - fh), "f"(lo_v - fl));
}

__device__ __forceinline__ float inv_sortable(uint32_t u) {
    return (u & 0x80000000u) ? __uint_as_float(u & 0x7FFFFFFFu) : __uint_as_float(~u);
}

#define LDSM_X4(r0, r1, r2, r3, addr) \
    asm volatile("ldmatrix.sync.aligned.m8n8.x4.shared.b16 {%0,%1,%2,%3}, [%4];" \
        : "=r"(r0), "=r"(r1), "=r"(r2), "=r"(r3) : "r"(addr))

#define MMA_BF16(c, a, b) \
    asm volatile("mma.sync.aligned.m16n8k16.row.col.f32.bf16.bf16.f32 " \
        "{%0,%1,%2,%3}, {%4,%5,%6,%7}, {%8,%9}, {%0,%1,%2,%3};" \
        : "+f"((c)[0]), "+f"((c)[1]), "+f"((c)[2]), "+f"((c)[3]) \
        : "r"((a)[0]), "r"((a)[1]), "r"((a)[2]), "r"((a)[3]), \
          "r"((b)[0]), "r"((b)[1]))

__device__ __forceinline__ void cp16(uint32_t dst, const void* src) {
    asm volatile("cp.async.cg.shared.global [%0], [%1], 16;"
                 :: "r"(dst), "l"(__cvta_generic_to_global(src)) : "memory");
}
#define CP_COMMIT() asm volatile("cp.async.commit_group;" ::: "memory")
#define CP_WAIT1()  asm volatile("cp.async.wait_group 1;" ::: "memory")
#define CP_WAIT0()  asm volatile("cp.async.wait_group 0;" ::: "memory")

// ---------------- 1) fused QKV projection + splits + transposes ---------------
// xsT stride 132 (multiple of 4) so per-d row reads are 16B-aligned LDS.128.
constexpr int XS_STRIDE = 132;
constexpr int PREP_XS   = 64 * XS_STRIDE;             // floats
constexpr int PREP_SMEM = (PREP_XS + 3 * 4096) * 4;   // 82944 B

__global__ __launch_bounds__(512) void prep_kernel(const float* __restrict__ x,
                                                   const float* __restrict__ Wq,
                                                   const float* __restrict__ Wk,
                                                   const float* __restrict__ Wv) {
    extern __shared__ float smf[];
    float* xsT = smf;                 // [64][132]
    float* Ws  = smf + PREP_XS;       // [3][64][64]

    const int tid  = threadIdx.x;
    const int row0 = blockIdx.x * 128;
    const int b    = row0 >> 12;
    const int l0   = row0 & (L - 1);

    for (int i = tid; i < 4096; i += 512) {
        Ws[i]        = Wq[i];
        Ws[4096 + i] = Wk[i];
        Ws[8192 + i] = Wv[i];
    }
    const int c = tid & 63, rg = tid >> 6;     // rg 0..7
    {
#pragma unroll
        for (int rr = 0; rr < 16; rr++) {
            int r = rg * 16 + rr;
            xsT[c * XS_STRIDE + r] = x[(size_t)(row0 + r) * 64 + c];
        }
    }
    __syncthreads();

    const size_t ot = ((size_t)b * 64 + c) * (size_t)L + l0 + rg * 16;
    const int xbase = rg * 16;

#pragma unroll
    for (int m = 0; m < 3; m++) {
        float acc[16];
#pragma unroll
        for (int i = 0; i < 16; i++) acc[i] = 0.f;
        const float* Wm = Ws + m * 4096 + c;
#pragma unroll 4
        for (int d = 0; d < 64; d++) {
            float w = Wm[d * 64];
            const float4* xv = (const float4*)(xsT + d * XS_STRIDE + xbase);
            float4 x0 = xv[0], x1 = xv[1], x2 = xv[2], x3 = xv[3];
            acc[0]  += x0.x * w; acc[1]  += x0.y * w;
            acc[2]  += x0.z * w; acc[3]  += x0.w * w;
            acc[4]  += x1.x * w; acc[5]  += x1.y * w;
            acc[6]  += x1.z * w; acc[7]  += x1.w * w;
            acc[8]  += x2.x * w; acc[9]  += x2.y * w;
            acc[10] += x2.z * w; acc[11] += x2.w * w;
            acc[12] += x3.x * w; acc[13] += x3.y * w;
            acc[14] += x3.z * w; acc[15] += x3.w * w;
        }

        if (m == 0) {            // Q: transposed fp32 + scaled hi/lo split
            float4* dq = (float4*)(g_QT + ot);
#pragma unroll
            for (int q = 0; q < 4; q++)
                dq[q] = make_float4(acc[4 * q], acc[4 * q + 1],
                                    acc[4 * q + 2], acc[4 * q + 3]);
#pragma unroll
            for (int rr = 0; rr < 16; rr++) {
                size_t idx = (size_t)(row0 + rg * 16 + rr) * 64 + c;
                float v = acc[rr] * 0.125f;
                __nv_bfloat16 h = __float2bfloat16(v);
                g_Qh[idx] = h;
                g_Ql[idx] = __float2bfloat16(v - __bfloat162float(h));
            }
        } else if (m == 1) {     // K: transposed fp32 + hi/lo split
            float4* dk = (float4*)(g_KT + ot);
#pragma unroll
            for (int q = 0; q < 4; q++)
                dk[q] = make_float4(acc[4 * q], acc[4 * q + 1],
                                    acc[4 * q + 2], acc[4 * q + 3]);
#pragma unroll
            for (int rr = 0; rr < 16; rr++) {
                size_t idx = (size_t)(row0 + rg * 16 + rr) * 64 + c;
                __nv_bfloat16 h = __float2bfloat16(acc[rr]);
                g_Kh[idx] = h;
                g_Kl[idx] = __float2bfloat16(acc[rr] - __bfloat162float(h));
            }
        } else {                 // V: transposed hi/lo split only
            uint32_t hw[8], lw[8];
#pragma unroll
            for (int j = 0; j < 8; j++)
                split2(acc[2 * j], acc[2 * j + 1], hw[j], lw[j]);
            uint4* dh = (uint4*)((char*)g_VTh + ot * 2);
            uint4* dl = (uint4*)((char*)g_VTl + ot * 2);
#pragma unroll
            for (int q = 0; q < 2; q++) {
                dh[q] = make_uint4(hw[4 * q], hw[4 * q + 1], hw[4 * q + 2], hw[4 * q + 3]);
                dl[q] = make_uint4(lw[4 * q], lw[4 * q + 1], lw[4 * q + 2], lw[4 * q + 3]);
            }
        }
    }
}

// ---------------- 2) K_reduce (radix select) + meanv folded in ----------------
// grid = B*D + B*8: first 512 blocks do kreduce, last 64 do meanv.
__global__ __launch_bounds__(256) void kreduce_kernel() {
    if (blockIdx.x >= B * D) {
        // ---- meanv: mean of V from transposed bf16 splits ----
        const int bid = blockIdx.x - B * D;
        const int b = bid >> 3, dg = bid & 7;
        const int tid = threadIdx.x;
        const int d = dg * 8 + (tid >> 5), lane = tid & 31;

        const size_t rowb = ((size_t)b * 64 + d) * (size_t)L;   // bf16 elems
        const uint4* rh = (const uint4*)((const char*)g_VTh + rowb * 2);
        const uint4* rl = (const uint4*)((const char*)g_VTl + rowb * 2);

        float s = 0.f;
#pragma unroll
        for (int it = 0; it < 16; it++) {
            uint4 h = rh[lane + 32 * it];
            uint4 lo = rl[lane + 32 * it];
            const uint32_t hw[4] = {h.x, h.y, h.z, h.w};
            const uint32_t lw[4] = {lo.x, lo.y, lo.z, lo.w};
#pragma unroll
            for (int q = 0; q < 4; q++) {
                s += __uint_as_float(hw[q] << 16) + __uint_as_float(hw[q] & 0xFFFF0000u);
                s += __uint_as_float(lw[q] << 16) + __uint_as_float(lw[q] & 0xFFFF0000u);
            }
        }
#pragma unroll
        for (int o = 16; o > 0; o >>= 1)
            s += __shfl_xor_sync(0xffffffffu, s, o);
        if (lane == 0) g_mean[b * 64 + d] = s * (1.0f / (float)L);
        return;
    }

    __shared__ uint32_t key[4096];
    __shared__ uint32_t hist[256];
    __shared__ uint32_t wsum[8];
    __shared__ float    fsum[8];
    __shared__ int      csum[8];
    __shared__ uint32_t sh_prefix;
    __shared__ int      sh_r;

    const int tid = threadIdx.x;
    const int b = blockIdx.x >> 6, d = blockIdx.x & 63;
    const float* Kr = g_KT + ((size_t)b * 64 + d) * (size_t)L;   // contiguous row

    for (int i = tid; i < 4096; i += 256) {
        uint32_t u = __float_as_uint(Kr[i]);
        key[i] = (u & 0x80000000u) ? ~u : (u | 0x80000000u);
    }
    if (tid == 0) { sh_r = NDROP; sh_prefix = 0; }
    __syncthreads();

    for (int shift = 24; shift >= 0; shift -= 8) {
        int r = sh_r;
        uint32_t pfx = sh_prefix;
        hist[tid] = 0;
        __syncthreads();
        for (int i = tid; i < 4096; i += 256) {
            uint32_t u = key[i];
            if (shift == 24 || (u >> (shift + 8)) == pfx)
                atomicAdd(&hist[(u >> shift) & 255u], 1u);
        }
        __syncthreads();
        uint32_t h = hist[tid], v = h;
#pragma unroll
        for (int o = 1; o < 32; o <<= 1) {
            uint32_t n = __shfl_up_sync(0xffffffffu, v, o);
            if ((tid & 31) >= o) v += n;
        }
        if ((tid & 31) == 31) wsum[tid >> 5] = v;
        __syncthreads();
        uint32_t woff = 0;
        for (int w = 0; w < (tid >> 5); w++) woff += wsum[w];
        uint32_t incl = v + woff, excl = incl - h;
        if ((uint32_t)r >= excl && (uint32_t)r < incl) {
            sh_prefix = (pfx << 8) | (uint32_t)tid;
            sh_r = r - (int)excl;
        }
        __syncthreads();
    }

    uint32_t vb = sh_prefix;
    float s = 0.f; int c = 0;
    for (int i = tid; i < 4096; i += 256) {
        uint32_t u = key[i];
        if (u > vb) { s += inv_sortable(u); c++; }
    }
#pragma unroll
    for (int o = 16; o > 0; o >>= 1) {
        s += __shfl_xor_sync(0xffffffffu, s, o);
        c += __shfl_xor_sync(0xffffffffu, c, o);
    }
    if ((tid & 31) == 0) { fsum[tid >> 5] = s; csum[tid >> 5] = c; }
    __syncthreads();
    if (tid == 0) {
        float st = 0.f; int ct = 0;
        for (int w = 0; w < 8; w++) { st += fsum[w]; ct += csum[w]; }
        g_Kred[b * 64 + d] =
            (st + (float)(LQ - ct) * inv_sortable(vb)) * (1.0f / (float)LQ);
    }
}

// ---------------- 3) wide sqk: keys for all (b,l), 128 blocks -----------------
// Per-l FMA chain over d identical to previous versions -> bitwise-identical keys.
__global__ __launch_bounds__(256) void sqk_kernel() {
    __shared__ float krs[64];
    const int tid = threadIdx.x;
    const int b = blockIdx.x >> 4, seg = blockIdx.x & 15;
    if (tid < 64) krs[tid] = g_Kred[b * 64 + tid];
    __syncthreads();

    const int l = seg * 256 + tid;
    const float* QT = g_QT + (size_t)b * 64 * (size_t)L + l;
    float acc = 0.f;
#pragma unroll 8
    for (int d = 0; d < 64; d++)
        acc += QT[(size_t)d * L] * krs[d];
    uint32_t u = __float_as_uint(acc);
    g_skey[b * L + l] = (u & 0x80000000u) ? ~u : (u | 0x80000000u);
}

// ---------------- 4) top-LQ selection: radix + aggregated scatter + tie scan --
__global__ __launch_bounds__(256) void select_kernel() {
    __shared__ uint32_t key[4096];
    __shared__ uint32_t hist[256];
    __shared__ uint32_t wsum[8];
    __shared__ uint32_t sh_prefix;
    __shared__ int      sh_r, nsel;

    const int tid = threadIdx.x, lane = tid & 31, warp = tid >> 5;
    const int b = blockIdx.x;
    const unsigned FULL = 0xffffffffu;

    for (int i = tid; i < 4096; i += 256)
        key[i] = g_skey[b * L + i];
    if (tid == 0) { sh_r = NDROP; sh_prefix = 0; nsel = 0; }
    __syncthreads();

    for (int shift = 24; shift >= 0; shift -= 8) {
        int r = sh_r;
        uint32_t pfx = sh_prefix;
        hist[tid] = 0;
        __syncthreads();
        for (int i = tid; i < 4096; i += 256) {
            uint32_t u = key[i];
            if (shift == 24 || (u >> (shift + 8)) == pfx)
                atomicAdd(&hist[(u >> shift) & 255u], 1u);
        }
        __syncthreads();
        uint32_t h = hist[tid], v = h;
#pragma unroll
        for (int o = 1; o < 32; o <<= 1) {
            uint32_t n = __shfl_up_sync(FULL, v, o);
            if (lane >= o) v += n;
        }
        if (lane == 31) wsum[warp] = v;
        __syncthreads();
        uint32_t woff = 0;
        for (int w = 0; w < warp; w++) woff += wsum[w];
        uint32_t incl = v + woff, excl = incl - h;
        if ((uint32_t)r >= excl && (uint32_t)r < incl) {
            sh_prefix = (pfx << 8) | (uint32_t)tid;
            sh_r = r - (int)excl;
        }
        __syncthreads();
    }

    const uint32_t vb = sh_prefix;

    // strict-above scatter: warp-aggregated atomic (set identical; order
    // irrelevant because rowslot keeps the sel<->slot mapping consistent)
#pragma unroll
    for (int it = 0; it < 16; it++) {
        int i = it * 256 + tid;
        bool f = (key[i] > vb);
        unsigned m = __ballot_sync(FULL, f);
        int rs = -1;
        if (m) {
            int leader = __ffs(m) - 1;
            int base = 0;
            if (lane == leader) base = atomicAdd(&nsel, __popc(m));
            base = __shfl_sync(FULL, base, leader);
            if (f) {
                int p = base + __popc(m & ((1u << lane) - 1u));
                g_sel[b * LQ + p] = i;
                rs = p;
            }
        }
        g_rowslot[b * L + i] = rs;
    }
    __syncthreads();

    // ties: single block-scan in index order (smallest indices first)
    {
        const int i0 = tid * 16;
        int cnt = 0;
#pragma unroll
        for (int j = 0; j < 16; j++) cnt += (key[i0 + j] == vb);
        int v = cnt;
#pragma unroll
        for (int o = 1; o < 32; o <<= 1) {
            int n = __shfl_up_sync(FULL, v, o);
            if (lane >= o) v += n;
        }
        if (lane == 31) wsum[warp] = (uint32_t)v;
        __syncthreads();
        int woff = 0;
        for (int w = 0; w < warp; w++) woff += (int)wsum[w];
        int r = v + woff - cnt;                 // exclusive rank in index order
        const int base = nsel, need = LQ - nsel;
#pragma unroll
        for (int j = 0; j < 16; j++) {
            int i = i0 + j;
            if (key[i] == vb) {
                if (r < need) {
                    g_sel[b * LQ + base + r] = i;
                    g_rowslot[b * L + i] = base + r;
                }
                r++;
            }
        }
    }
}

// ---------------- 5) persistent HMMA flash attention (pipelined) ---------------
// Contiguous task ranges (tile-major): a block's tasks share q-tiles, so Q
// gather + Q-LDSM run once per tile instead of once per task. Per-task math
// and slab targets identical -> bitwise-identical output.
constexpr int S_QL   = 36864;
constexpr int S_K0   = 73728;
constexpr int SO_VH  = 36864;        // within stage
constexpr int STG    = 71680;        // 2*18432 + 2*17408
constexpr int SMEM_ATTN = S_K0 + 2 * STG;   // 217088

__device__ __forceinline__ void stage_load(uint32_t sbase, int b, int k0, int tid) {
#pragma unroll
    for (int c = 0; c < 4; c++) {
        int ch = tid + 256 * c;                 // 0..1023
        int row = ch >> 3, off = ch & 7;
        size_t gi = ((size_t)b * L + k0 + row) * 64 + off * 8;
        uint32_t dk = sbase + (uint32_t)(row * 144 + off * 16);
        cp16(dk,          g_Kh + gi);
        cp16(dk + 18432u, g_Kl + gi);
    }
#pragma unroll
    for (int c = 0; c < 4; c++) {
        int ch = tid + 256 * c;                 // 0..1023
        int dd = ch >> 4, off = ch & 15;
        size_t gi = ((size_t)b * 64 + dd) * (size_t)L + k0 + off * 8;
        uint32_t dv = sbase + (uint32_t)SO_VH + (uint32_t)(dd * 272 + off * 16);
        cp16(dv,          g_VTh + gi);
        cp16(dv + 17408u, g_VTl + gi);
    }
}

#define S_CHUNK(sarr, cc, kab) do { \
    uint32_t bh[4], bl[4]; \
    LDSM_X4(bh[0], bh[1], bh[2], bh[3], (kab) + (cc) * 32); \
    LDSM_X4(bl[0], bl[1], bl[2], bl[3], (kab) + (cc) * 32 + 18432u); \
    MMA_BF16((sarr)[0][0], qh[0][cc], bh); \
    MMA_BF16((sarr)[1][0], qh[1][cc], bh); \
    MMA_BF16((sarr)[0][1], qh[0][cc], bh + 2); \
    MMA_BF16((sarr)[1][1], qh[1][cc], bh + 2); \
    MMA_BF16((sarr)[0][0], qh[0][cc], bl); \
    MMA_BF16((sarr)[1][0], qh[1][cc], bl); \
    MMA_BF16((sarr)[0][1], qh[0][cc], bl + 2); \
    MMA_BF16((sarr)[1][1], qh[1][cc], bl + 2); \
    MMA_BF16((sarr)[0][0], ql[0][cc], bh); \
    MMA_BF16((sarr)[1][0], ql[1][cc], bh); \
    MMA_BF16((sarr)[0][1], ql[0][cc], bh + 2); \
    MMA_BF16((sarr)[1][1], ql[1][cc], bh + 2); \
} while (0)

#define PV_CHUNK(jp, vab) do { \
    uint32_t bvh[4], bvl[4]; \
    uint32_t a_ = (vab) + (uint32_t)((jp) * 16) * 272; \
    LDSM_X4(bvh[0], bvh[1], bvh[2], bvh[3], a_); \
    LDSM_X4(bvl[0], bvl[1], bvl[2], bvl[3], a_ + 17408u); \
    MMA_BF16(oacc[0][2 * (jp)],     pah[0], bvh); \
    MMA_BF16(oacc[1][2 * (jp)],     pah[1], bvh); \
    MMA_BF16(oacc[0][2 * (jp) + 1], pah[0], bvh + 2); \
    MMA_BF16(oacc[1][2 * (jp) + 1], pah[1], bvh + 2); \
    MMA_BF16(oacc[0][2 * (jp)],     pah[0], bvl); \
    MMA_BF16(oacc[1][2 * (jp)],     pah[1], bvl); \
    MMA_BF16(oacc[0][2 * (jp) + 1], pah[0], bvl + 2); \
    MMA_BF16(oacc[1][2 * (jp) + 1], pah[1], bvl + 2); \
    MMA_BF16(oacc[0][2 * (jp)],     pal[0], bvh); \
    MMA_BF16(oacc[1][2 * (jp)],     pal[1], bvh); \
    MMA_BF16(oacc[0][2 * (jp) + 1], pal[0], bvh + 2); \
    MMA_BF16(oacc[1][2 * (jp) + 1], pal[1], bvh + 2); \
} while (0)

__global__ __launch_bounds__(256, 1) void attn_kernel() {
    extern __shared__ __align__(16) char sm[];

    const int tid = threadIdx.x, wid = tid >> 5, lane = tid & 31;
    const uint32_t smb = smem_u32(sm);

    const int start = (blockIdx.x * TASKS) / NBLK;
    const int stop  = ((blockIdx.x + 1) * TASKS) / NBLK;

    const uint32_t koff = (uint32_t)((lane & 7) + ((lane >> 4) & 1) * 8) * 144 +
                          ((lane >> 3) & 1) * 16;
    const uint32_t voff = (uint32_t)((lane & 7) + ((lane >> 4) & 1) * 8) * 272 +
                          ((lane >> 3) & 1) * 16;

    uint32_t qh[2][4][4], ql[2][4][4];   // persist across same-tile tasks
    int prev_tile = -1;

    for (int tsk = start; tsk < stop; tsk++) {
        const int tile = tsk >> 3, slice = tsk & 7;
        const int b = tile / NQT, qt = tile - b * NQT;
        const int k0b = slice * 512;
        const bool newQ = (tile != prev_tile);
        prev_tile = tile;

        if (newQ) {
            // Q gather (hi/lo) via cp.async; g_sel read inline (no smem qidx)
#pragma unroll
            for (int c = 0; c < 8; c++) {
                int ch = tid + 256 * c;          // 0..2047
                int row = ch >> 3, off = ch & 7;
                int g = qt * 256 + row;
                int sel = g_sel[b * LQ + (g < LQ ? g : LQ - 1)];
                size_t gi = ((size_t)b * L + sel) * 64 + off * 8;
                uint32_t dq = smb + (uint32_t)(row * 144 + off * 16);
                cp16(dq,                  g_Qh + gi);
                cp16(dq + (uint32_t)S_QL, g_Ql + gi);
            }
            CP_COMMIT();
        }
        stage_load(smb + S_K0, b, k0b, tid);     // stage 0
        CP_COMMIT();

        if (newQ) {
            CP_WAIT1();                           // Q complete (s0 may pend)
            __syncthreads();
#pragma unroll
            for (int mt = 0; mt < 2; mt++) {
                uint32_t rsel = (uint32_t)(wid * 32 + mt * 16 + (lane & 7) +
                                           ((lane >> 3) & 1) * 8);
                uint32_t csel = ((lane >> 4) & 1) * 16;
#pragma unroll
                for (int c = 0; c < 4; c++) {
                    uint32_t a = smb + rsel * 144 + c * 32 + csel;
                    LDSM_X4(qh[mt][c][0], qh[mt][c][1], qh[mt][c][2], qh[mt][c][3], a);
                    LDSM_X4(ql[mt][c][0], ql[mt][c][1], ql[mt][c][2], ql[mt][c][3],
                            a + (uint32_t)S_QL);
                }
            }
        }

        float oacc[2][8][4];
#pragma unroll
        for (int mt = 0; mt < 2; mt++)
#pragma unroll
            for (int j = 0; j < 8; j++)
#pragma unroll
                for (int i = 0; i < 4; i++) oacc[mt][j][i] = 0.f;
        float ls[2][2] = {{0.f, 0.f}, {0.f, 0.f}};

        for (int t = 0; t < 4; t++) {
            if (t < 3) {
                stage_load(smb + S_K0 + (uint32_t)(((t + 1) & 1) * STG),
                           b, k0b + (t + 1) * 128, tid);
                CP_COMMIT();
                CP_WAIT1();                       // stage t complete
            } else {
                CP_WAIT0();
            }
            __syncthreads();

            const uint32_t sb = smb + S_K0 + (uint32_t)((t & 1) * STG);
            const uint32_t kabase = sb + koff;
            const uint32_t vabase = sb + (uint32_t)SO_VH + voff;

            // ---- prolog: S(kc=0) into s[0] ----
            float s[2][2][2][4];
#pragma unroll
            for (int mt = 0; mt < 2; mt++)
#pragma unroll
                for (int j = 0; j < 2; j++)
#pragma unroll
                    for (int i = 0; i < 4; i++) s[0][mt][j][i] = 0.f;
#pragma unroll
            for (int c = 0; c < 4; c++) S_CHUNK(s[0], c, kabase);

#pragma unroll
            for (int kc = 0; kc < 8; kc++) {
                const int cur = kc & 1, nxt = cur ^ 1;

                // ---- softmax of kc (data ready since mid iter kc-1) ----
                uint32_t pah[2][4], pal[2][4];
#pragma unroll
                for (int mt = 0; mt < 2; mt++) {
                    float e00 = __expf(s[cur][mt][0][0]), e01 = __expf(s[cur][mt][0][1]);
                    float e02 = __expf(s[cur][mt][0][2]), e03 = __expf(s[cur][mt][0][3]);
                    float e10 = __expf(s[cur][mt][1][0]), e11 = __expf(s[cur][mt][1][1]);
                    float e12 = __expf(s[cur][mt][1][2]), e13 = __expf(s[cur][mt][1][3]);
                    ls[mt][0] += e00 + e01 + e10 + e11;
                    ls[mt][1] += e02 + e03 + e12 + e13;
                    psplit(e00, e01, pah[mt][0], pal[mt][0]);
                    psplit(e02, e03, pah[mt][1], pal[mt][1]);
                    psplit(e10, e11, pah[mt][2], pal[mt][2]);
                    psplit(e12, e13, pah[mt][3], pal[mt][3]);
                }

                const uint32_t vac = vabase + (uint32_t)(kc * 32);
                if (kc < 7) {
#pragma unroll
                    for (int mt = 0; mt < 2; mt++)
#pragma unroll
                        for (int j = 0; j < 2; j++)
#pragma unroll
                            for (int i = 0; i < 4; i++) s[nxt][mt][j][i] = 0.f;
                    const uint32_t kan = kabase + (uint32_t)(16 * (kc + 1)) * 144;
#pragma unroll
                    for (int i = 0; i < 4; i++) {
                        S_CHUNK(s[nxt], i, kan);   // next-kc S, fills tensor pipe
                        PV_CHUNK(i, vac);          // current-kc PV
                    }
                } else {
#pragma unroll
                    for (int i = 0; i < 4; i++) PV_CHUNK(i, vac);
                }
            }
            __syncthreads();
        }

        // epilogue: partial (O, l) to this slice's slab (no atomics)
#pragma unroll
        for (int mt = 0; mt < 2; mt++) {
            float l0 = ls[mt][0], l1 = ls[mt][1];
            l0 += __shfl_xor_sync(0xffffffffu, l0, 1);
            l0 += __shfl_xor_sync(0xffffffffu, l0, 2);
            l1 += __shfl_xor_sync(0xffffffffu, l1, 1);
            l1 += __shfl_xor_sync(0xffffffffu, l1, 2);

            const int r0 = wid * 32 + mt * 16 + (lane >> 2), r1 = r0 + 8;
            const size_t slab = (size_t)(slice * B + b) * ROWS;
            const int gq0 = qt * 256 + r0, gq1 = qt * 256 + r1;
            float* O0 = g_Oacc + (slab + gq0) * 64 + (lane & 3) * 2;
            float* O1 = g_Oacc + (slab + gq1) * 64 + (lane & 3) * 2;
#pragma unroll
            for (int jd = 0; jd < 8; jd++) {
                *(float2*)(O0 + jd * 8) = make_float2(oacc[mt][jd][0], oacc[mt][jd][1]);
                *(float2*)(O1 + jd * 8) = make_float2(oacc[mt][jd][2], oacc[mt][jd][3]);
            }
            if ((lane & 3) == 0) {
                g_lacc[slab + gq0] = l0;
                g_lacc[slab + gq1] = l1;
            }
        }
    }
}

// ---------------- 6) output: mean or normalized attention per row -------------
__global__ __launch_bounds__(256) void output_kernel(float* __restrict__ out) {
    int u = blockIdx.x * 256 + threadIdx.x;       // float4 units, B*L*16 total
    int d4 = u & 15;
    int row = u >> 4;                              // b*L + l
    int b = row >> 12;
    int slot = g_rowslot[row];

    float4 w;
    if (slot < 0) {
        w = ((const float4*)(g_mean + b * 64))[d4];
    } else {
        float4 o = make_float4(0.f, 0.f, 0.f, 0.f);
        float l = 0.f;
#pragma unroll
        for (int s = 0; s < NSLICE; s++) {
            size_t base = (size_t)(s * B + b) * ROWS + slot;
            float4 p = ((const float4*)(g_Oacc + base * 64))[d4];
            o.x += p.x; o.y += p.y; o.z += p.z; o.w += p.w;
            l += g_lacc[base];
        }
        float inv = 1.0f / l;
        w = make_float4(o.x * inv, o.y * inv, o.z * inv, o.w * inv);
    }
    ((float4*)out)[u] = w;
}

// ---------------- launcher ----------------------------------------------------
extern "C" void kernel_launch(void* const* d_in, const int* in_sizes, int n_in,
                              void* d_out, int out_size) {
    const float* x  = (const float*)d_in[0];
    const float* Wq = (const float*)d_in[1];
    const float* Wk = (const float*)d_in[2];
    const float* Wv = (const float*)d_in[3];
    float* out = (float*)d_out;

    cudaFuncSetAttribute(prep_kernel,
                         cudaFuncAttributeMaxDynamicSharedMemorySize, PREP_SMEM);
    cudaFuncSetAttribute(attn_kernel,
                         cudaFuncAttributeMaxDynamicSharedMemorySize, SMEM_ATTN);

    prep_kernel<<<(B * L) / 128, 512, PREP_SMEM>>>(x, Wq, Wk, Wv);   // 1
    kreduce_kernel<<<B * D + B * 8, 256>>>();                        // 2 (+meanv)
    sqk_kernel<<<B * 16, 256>>>();                                   // 3
    select_kernel<<<B, 256>>>();                                     // 4 <- profiled
    attn_kernel<<<NBLK, 256, SMEM_ATTN>>>();                         // 5
    output_kernel<<<(B * L * 16) / 256, 256>>>(out);                 // 6
}